// round 3
// baseline (speedup 1.0000x reference)
#include <cuda_runtime.h>
#include <math.h>
#include <stdint.h>

#define NSEQ 1024
#define DMOD 512
#define NHEAD 16
#define HDIM 32
#define DZ 128
#define NN (NSEQ*NSEQ)
#define QSCALE 0.17677669529663687f

__device__ float g_sln[NSEQ*DMOD];
__device__ float g_q[NHEAD*NSEQ*HDIM];
__device__ float g_k[NHEAD*NSEQ*HDIM];
__device__ float g_v[NHEAD*NSEQ*HDIM];
__device__ float g_gate[NSEQ*DMOD];
__device__ float g_o[NSEQ*DMOD];
__device__ float g_scores[NHEAD*NN];
__device__ float g_wzp[DZ*NHEAD];
__device__ float g_alpha[NHEAD];
__device__ float g_beta[NHEAD];

__global__ void prep_kernel(const float* __restrict__ Wz,
                            const float* __restrict__ zw,
                            const float* __restrict__ zb)
{
    int t = threadIdx.x;
    for (int i = t; i < DZ*NHEAD; i += blockDim.x)
        g_wzp[i] = zw[i >> 4] * Wz[i];
    if (t < NHEAD) {
        float a = 0.f, b = 0.f;
        for (int c = 0; c < DZ; c++) {
            float wv = Wz[c*NHEAD + t];
            a += zw[c] * wv;
            b += zb[c] * wv;
        }
        g_alpha[t] = a;
        g_beta[t]  = b;
    }
}

__global__ __launch_bounds__(128) void ln_s_kernel(const float* __restrict__ s,
                                                   const float* __restrict__ w,
                                                   const float* __restrict__ b)
{
    __shared__ float sred[8];
    __shared__ float s_mu, s_rstd;
    int row = blockIdx.x, tid = threadIdx.x;
    float4 v = *(const float4*)&s[row*DMOD + tid*4];
    float sum = v.x + v.y + v.z + v.w;
    float ssq = v.x*v.x + v.y*v.y + v.z*v.z + v.w*v.w;
    #pragma unroll
    for (int o = 16; o; o >>= 1) {
        sum += __shfl_xor_sync(0xffffffffu, sum, o);
        ssq += __shfl_xor_sync(0xffffffffu, ssq, o);
    }
    int lane = tid & 31, wid = tid >> 5;
    if (lane == 0) { sred[wid] = sum; sred[4 + wid] = ssq; }
    __syncthreads();
    if (tid == 0) {
        float a = sred[0]+sred[1]+sred[2]+sred[3];
        float q = sred[4]+sred[5]+sred[6]+sred[7];
        float mu = a * (1.f/DMOD);
        float var = q * (1.f/DMOD) - mu*mu;
        s_mu = mu; s_rstd = rsqrtf(var + 1e-5f);
    }
    __syncthreads();
    float mu = s_mu, rstd = s_rstd;
    float4 wv = *(const float4*)&w[tid*4];
    float4 bv = *(const float4*)&b[tid*4];
    float4 o;
    o.x = (v.x-mu)*rstd*wv.x + bv.x;
    o.y = (v.y-mu)*rstd*wv.y + bv.y;
    o.z = (v.z-mu)*rstd*wv.z + bv.z;
    o.w = (v.w-mu)*rstd*wv.w + bv.w;
    *(float4*)&g_sln[row*DMOD + tid*4] = o;
}

// modes: 0 q=(A@B+bq)*QSCALE  1 k=A@B  2 v=A@B  (all -> [h][n][hd])
//        3 gate=sigmoid(A@B) -> [n][d]   4 out=(g_o*g_gate)@B -> Cout [n][d]
__global__ __launch_bounds__(256) void gemm_ep_kernel(const float* __restrict__ B,
                                                      const float* __restrict__ bias,
                                                      float* __restrict__ Cout,
                                                      int mode)
{
    __shared__ float As[16][64];
    __shared__ float Bs[16][64];
    int tid = threadIdx.x;
    int tx = tid & 15, ty = tid >> 4;
    int row0 = blockIdx.y * 64, col0 = blockIdx.x * 64;
    const float* A = (mode == 4) ? g_o : g_sln;
    int arow = tid >> 2, ak = (tid & 3) << 2;
    int bk = tid >> 4, bc = (tid & 15) << 2;
    float acc[4][4] = {};
    for (int k0 = 0; k0 < DMOD; k0 += 16) {
        float4 av = *(const float4*)&A[(row0 + arow)*DMOD + k0 + ak];
        if (mode == 4) {
            float4 gv = *(const float4*)&g_gate[(row0 + arow)*DMOD + k0 + ak];
            av.x *= gv.x; av.y *= gv.y; av.z *= gv.z; av.w *= gv.w;
        }
        float4 bv = *(const float4*)&B[(k0 + bk)*DMOD + col0 + bc];
        __syncthreads();
        As[ak+0][arow] = av.x; As[ak+1][arow] = av.y;
        As[ak+2][arow] = av.z; As[ak+3][arow] = av.w;
        *(float4*)&Bs[bk][bc] = bv;
        __syncthreads();
        #pragma unroll
        for (int kk = 0; kk < 16; kk++) {
            float4 a4 = *(const float4*)&As[kk][ty << 2];
            float4 b4 = *(const float4*)&Bs[kk][tx << 2];
            float ar[4] = {a4.x, a4.y, a4.z, a4.w};
            float br[4] = {b4.x, b4.y, b4.z, b4.w};
            #pragma unroll
            for (int i = 0; i < 4; i++)
                #pragma unroll
                for (int j = 0; j < 4; j++)
                    acc[i][j] = fmaf(ar[i], br[j], acc[i][j]);
        }
    }
    int row = row0 + (ty << 2), col = col0 + (tx << 2);
    if (mode <= 2) {
        float* dst = (mode == 0) ? g_q : (mode == 1 ? g_k : g_v);
        float bb[4] = {0.f,0.f,0.f,0.f};
        if (mode == 0) {
            float4 bia = *(const float4*)&bias[col];
            bb[0]=bia.x; bb[1]=bia.y; bb[2]=bia.z; bb[3]=bia.w;
        }
        #pragma unroll
        for (int i = 0; i < 4; i++)
            #pragma unroll
            for (int j = 0; j < 4; j++) {
                int cc = col + j;
                float v = acc[i][j];
                if (mode == 0) v = (v + bb[j]) * QSCALE;
                dst[((cc >> 5)*NSEQ + (row + i))*HDIM + (cc & 31)] = v;
            }
    } else if (mode == 3) {
        #pragma unroll
        for (int i = 0; i < 4; i++)
            #pragma unroll
            for (int j = 0; j < 4; j++)
                g_gate[(row+i)*DMOD + col+j] = 1.f/(1.f + __expf(-acc[i][j]));
    } else {
        #pragma unroll
        for (int i = 0; i < 4; i++)
            *(float4*)&Cout[(row+i)*DMOD + col] =
                make_float4(acc[i][0], acc[i][1], acc[i][2], acc[i][3]);
    }
}

// fused LN(z)@Wz -> g_scores[h][q][k]; single pass over z (512 MB)
__global__ __launch_bounds__(256) void zbias_kernel(const float* __restrict__ z)
{
    __shared__ float wz_s[DZ][NHEAD];
    __shared__ float ab_s[2*NHEAD];
    __shared__ float zt[8][32][33];
    int tid = threadIdx.x;
    int lane = tid & 31, w = tid >> 5;
    for (int i = tid; i < DZ*NHEAD; i += 256)
        wz_s[i >> 4][i & 15] = g_wzp[i];
    if (tid < 32) ab_s[tid] = (tid < 16) ? g_alpha[tid] : g_beta[tid - 16];
    __syncthreads();

    int row0w = blockIdx.x*256 + w*32;
    const float* zwarp = z + (size_t)row0w * DZ;
    float acc[NHEAD];
    #pragma unroll
    for (int h = 0; h < NHEAD; h++) acc[h] = 0.f;
    float sum = 0.f, ssq = 0.f;

    for (int ch = 0; ch < 4; ch++) {
        #pragma unroll
        for (int r = 0; r < 32; r++)
            zt[w][r][lane] = zwarp[(size_t)r*DZ + ch*32 + lane];
        __syncwarp();
        #pragma unroll
        for (int c = 0; c < 32; c++) {
            float val = zt[w][lane][c];
            sum += val; ssq += val*val;
            const float* wrow = &wz_s[ch*32 + c][0];
            #pragma unroll
            for (int h4 = 0; h4 < 4; h4++) {
                float4 wv = *(const float4*)&wrow[h4*4];
                acc[h4*4+0] = fmaf(val, wv.x, acc[h4*4+0]);
                acc[h4*4+1] = fmaf(val, wv.y, acc[h4*4+1]);
                acc[h4*4+2] = fmaf(val, wv.z, acc[h4*4+2]);
                acc[h4*4+3] = fmaf(val, wv.w, acc[h4*4+3]);
            }
        }
        __syncwarp();
    }
    float mu = sum * (1.f/DZ);
    float var = ssq * (1.f/DZ) - mu*mu;
    float rstd = rsqrtf(var + 1e-5f);
    int row = row0w + lane;
    #pragma unroll
    for (int h = 0; h < NHEAD; h++)
        g_scores[h*NN + row] = rstd*(acc[h] - mu*ab_s[h]) + ab_s[16+h];
}

// S[h][q][k] = q.k (q pre-scaled) + zb (in place on g_scores)
__global__ __launch_bounds__(256) void score_kernel()
{
    __shared__ float Qs[32][64];
    __shared__ float Ks[32][64];
    int tid = threadIdx.x;
    int tx = tid & 15, ty = tid >> 4;
    int k0 = blockIdx.x*64, q0 = blockIdx.y*64, h = blockIdx.z;
    const float* qb = g_q + h*NSEQ*HDIM;
    const float* kb = g_k + h*NSEQ*HDIM;
    int arow = tid >> 2, ak = (tid & 3) << 2;
    float4 qa = *(const float4*)&qb[(q0+arow)*HDIM + ak];
    float4 qc = *(const float4*)&qb[(q0+arow)*HDIM + ak + 16];
    float4 ka = *(const float4*)&kb[(k0+arow)*HDIM + ak];
    float4 kc = *(const float4*)&kb[(k0+arow)*HDIM + ak + 16];
    Qs[ak+0][arow]=qa.x; Qs[ak+1][arow]=qa.y; Qs[ak+2][arow]=qa.z; Qs[ak+3][arow]=qa.w;
    Qs[ak+16][arow]=qc.x; Qs[ak+17][arow]=qc.y; Qs[ak+18][arow]=qc.z; Qs[ak+19][arow]=qc.w;
    Ks[ak+0][arow]=ka.x; Ks[ak+1][arow]=ka.y; Ks[ak+2][arow]=ka.z; Ks[ak+3][arow]=ka.w;
    Ks[ak+16][arow]=kc.x; Ks[ak+17][arow]=kc.y; Ks[ak+18][arow]=kc.z; Ks[ak+19][arow]=kc.w;
    __syncthreads();
    float acc[4][4] = {};
    #pragma unroll
    for (int kk = 0; kk < 32; kk++) {
        float4 a4 = *(const float4*)&Qs[kk][ty << 2];
        float4 b4 = *(const float4*)&Ks[kk][tx << 2];
        float ar[4] = {a4.x,a4.y,a4.z,a4.w};
        float br[4] = {b4.x,b4.y,b4.z,b4.w};
        #pragma unroll
        for (int i = 0; i < 4; i++)
            #pragma unroll
            for (int j = 0; j < 4; j++)
                acc[i][j] = fmaf(ar[i], br[j], acc[i][j]);
    }
    float* sp = g_scores + (size_t)h*NN;
    int row = q0 + (ty << 2), col = k0 + (tx << 2);
    #pragma unroll
    for (int i = 0; i < 4; i++) {
        float4 zb4 = *(float4*)&sp[(row+i)*NSEQ + col];
        zb4.x += acc[i][0]; zb4.y += acc[i][1];
        zb4.z += acc[i][2]; zb4.w += acc[i][3];
        *(float4*)&sp[(row+i)*NSEQ + col] = zb4;
    }
}

__global__ __launch_bounds__(256) void softmax_kernel()
{
    int row = blockIdx.x*8 + (threadIdx.x >> 5);
    int lane = threadIdx.x & 31;
    float4* p = (float4*)(g_scores + (size_t)row*NSEQ);
    float4 v[8];
    float mx = -1e30f;
    #pragma unroll
    for (int i = 0; i < 8; i++) {
        v[i] = p[i*32 + lane];
        mx = fmaxf(mx, fmaxf(fmaxf(v[i].x, v[i].y), fmaxf(v[i].z, v[i].w)));
    }
    #pragma unroll
    for (int o = 16; o; o >>= 1) mx = fmaxf(mx, __shfl_xor_sync(0xffffffffu, mx, o));
    float sum = 0.f;
    #pragma unroll
    for (int i = 0; i < 8; i++) {
        v[i].x = __expf(v[i].x - mx); v[i].y = __expf(v[i].y - mx);
        v[i].z = __expf(v[i].z - mx); v[i].w = __expf(v[i].w - mx);
        sum += v[i].x + v[i].y + v[i].z + v[i].w;
    }
    #pragma unroll
    for (int o = 16; o; o >>= 1) sum += __shfl_xor_sync(0xffffffffu, sum, o);
    float inv = 1.f / sum;
    #pragma unroll
    for (int i = 0; i < 8; i++) {
        v[i].x *= inv; v[i].y *= inv; v[i].z *= inv; v[i].w *= inv;
        p[i*32 + lane] = v[i];
    }
}

// o[q][h*32+hd] = sum_k S[h][q][k] * v[h][k][hd]
__global__ __launch_bounds__(256) void av_kernel()
{
    __shared__ float Ss[64][65];
    __shared__ float Vs[64][36];
    int tid = threadIdx.x;
    int q0 = blockIdx.x*64, h = blockIdx.y;
    const float* sp = g_scores + (size_t)h*NN;
    const float* vp = g_v + h*NSEQ*HDIM;
    int ty = tid >> 3, tx = tid & 7;
    int sr = tid >> 2, sc = (tid & 3) << 4;
    int fr = tid >> 2, fc = (tid & 3) << 3;
    float acc[2][4] = {};
    for (int kb = 0; kb < NSEQ; kb += 64) {
        #pragma unroll
        for (int i = 0; i < 4; i++) {
            float4 s4 = *(const float4*)&sp[(q0+sr)*NSEQ + kb + sc + i*4];
            Ss[sr][sc+i*4+0]=s4.x; Ss[sr][sc+i*4+1]=s4.y;
            Ss[sr][sc+i*4+2]=s4.z; Ss[sr][sc+i*4+3]=s4.w;
        }
        #pragma unroll
        for (int i = 0; i < 2; i++)
            *(float4*)&Vs[fr][fc+i*4] = *(const float4*)&vp[(kb+fr)*HDIM + fc + i*4];
        __syncthreads();
        #pragma unroll
        for (int kk = 0; kk < 64; kk++) {
            float a0 = Ss[ty*2+0][kk];
            float a1 = Ss[ty*2+1][kk];
            float4 b = *(const float4*)&Vs[kk][tx << 2];
            acc[0][0]=fmaf(a0,b.x,acc[0][0]); acc[0][1]=fmaf(a0,b.y,acc[0][1]);
            acc[0][2]=fmaf(a0,b.z,acc[0][2]); acc[0][3]=fmaf(a0,b.w,acc[0][3]);
            acc[1][0]=fmaf(a1,b.x,acc[1][0]); acc[1][1]=fmaf(a1,b.y,acc[1][1]);
            acc[1][2]=fmaf(a1,b.z,acc[1][2]); acc[1][3]=fmaf(a1,b.w,acc[1][3]);
        }
        __syncthreads();
    }
    #pragma unroll
    for (int r = 0; r < 2; r++)
        *(float4*)&g_o[(q0 + ty*2 + r)*DMOD + h*HDIM + (tx << 2)] =
            make_float4(acc[r][0], acc[r][1], acc[r][2], acc[r][3]);
}

extern "C" void kernel_launch(void* const* d_in, const int* in_sizes, int n_in,
                              void* d_out, int out_size)
{
    const float* s   = (const float*)d_in[0];
    const float* z   = (const float*)d_in[1];
    const float* nsw = (const float*)d_in[2];
    const float* nsb = (const float*)d_in[3];
    const float* Wq  = (const float*)d_in[4];
    const float* bq  = (const float*)d_in[5];
    const float* Wk  = (const float*)d_in[6];
    const float* Wv  = (const float*)d_in[7];
    const float* Wg  = (const float*)d_in[8];
    const float* zw  = (const float*)d_in[9];
    const float* zb  = (const float*)d_in[10];
    const float* Wz  = (const float*)d_in[11];
    const float* Wo  = (const float*)d_in[12];
    float* out = (float*)d_out;

    prep_kernel<<<1, 256>>>(Wz, zw, zb);
    ln_s_kernel<<<NSEQ, 128>>>(s, nsw, nsb);
    dim3 gg(DMOD/64, NSEQ/64);
    gemm_ep_kernel<<<gg, 256>>>(Wq, bq, nullptr, 0);
    gemm_ep_kernel<<<gg, 256>>>(Wk, nullptr, nullptr, 1);
    gemm_ep_kernel<<<gg, 256>>>(Wv, nullptr, nullptr, 2);
    gemm_ep_kernel<<<gg, 256>>>(Wg, nullptr, nullptr, 3);
    zbias_kernel<<<NN/256, 256>>>(z);
    score_kernel<<<dim3(NSEQ/64, NSEQ/64, NHEAD), 256>>>();
    softmax_kernel<<<NHEAD*NSEQ/8, 256>>>();
    av_kernel<<<dim3(NSEQ/64, NHEAD), 256>>>();
    gemm_ep_kernel<<<gg, 256>>>(Wo, nullptr, out, 4);
}

// round 4
// speedup vs baseline: 1.2555x; 1.2555x over previous
#include <cuda_runtime.h>
#include <math.h>
#include <stdint.h>

#define NSEQ 1024
#define DMOD 512
#define NHEAD 16
#define HDIM 32
#define DZ 128
#define NN (NSEQ*NSEQ)
#define QSCALE 0.17677669529663687f

__device__ float g_sln[NSEQ*DMOD];
__device__ float g_q[NHEAD*NSEQ*HDIM];
__device__ float g_k[NHEAD*NSEQ*HDIM];
__device__ float g_v[NHEAD*NSEQ*HDIM];
__device__ float g_gate[NSEQ*DMOD];
__device__ float g_o[NSEQ*DMOD];
__device__ float g_scores[NHEAD*NN];   // holds zb only (flash never materializes scores)
__device__ float g_wzp[DZ*NHEAD];
__device__ float g_alpha[NHEAD];
__device__ float g_beta[NHEAD];

__global__ void prep_kernel(const float* __restrict__ Wz,
                            const float* __restrict__ zw,
                            const float* __restrict__ zb)
{
    int t = threadIdx.x;
    for (int i = t; i < DZ*NHEAD; i += blockDim.x)
        g_wzp[i] = zw[i >> 4] * Wz[i];
    if (t < NHEAD) {
        float a = 0.f, b = 0.f;
        for (int c = 0; c < DZ; c++) {
            float wv = Wz[c*NHEAD + t];
            a += zw[c] * wv;
            b += zb[c] * wv;
        }
        g_alpha[t] = a;
        g_beta[t]  = b;
    }
}

__global__ __launch_bounds__(128) void ln_s_kernel(const float* __restrict__ s,
                                                   const float* __restrict__ w,
                                                   const float* __restrict__ b)
{
    __shared__ float sred[8];
    __shared__ float s_mu, s_rstd;
    int row = blockIdx.x, tid = threadIdx.x;
    float4 v = *(const float4*)&s[row*DMOD + tid*4];
    float sum = v.x + v.y + v.z + v.w;
    float ssq = v.x*v.x + v.y*v.y + v.z*v.z + v.w*v.w;
    #pragma unroll
    for (int o = 16; o; o >>= 1) {
        sum += __shfl_xor_sync(0xffffffffu, sum, o);
        ssq += __shfl_xor_sync(0xffffffffu, ssq, o);
    }
    int lane = tid & 31, wid = tid >> 5;
    if (lane == 0) { sred[wid] = sum; sred[4 + wid] = ssq; }
    __syncthreads();
    if (tid == 0) {
        float a = sred[0]+sred[1]+sred[2]+sred[3];
        float q = sred[4]+sred[5]+sred[6]+sred[7];
        float mu = a * (1.f/DMOD);
        float var = q * (1.f/DMOD) - mu*mu;
        s_mu = mu; s_rstd = rsqrtf(var + 1e-5f);
    }
    __syncthreads();
    float mu = s_mu, rstd = s_rstd;
    float4 wv = *(const float4*)&w[tid*4];
    float4 bv = *(const float4*)&b[tid*4];
    float4 o;
    o.x = (v.x-mu)*rstd*wv.x + bv.x;
    o.y = (v.y-mu)*rstd*wv.y + bv.y;
    o.z = (v.z-mu)*rstd*wv.z + bv.z;
    o.w = (v.w-mu)*rstd*wv.w + bv.w;
    *(float4*)&g_sln[row*DMOD + tid*4] = o;
}

// Double-buffered 64x64x512 GEMM.
// mode_sel=-1: mode=blockIdx.z (0 q,1 k,2 v,3 gate). mode_sel=4: out=(g_o*g_gate)@Wo.
__global__ __launch_bounds__(256) void gemm_fused(
    const float* __restrict__ Wq, const float* __restrict__ Wk,
    const float* __restrict__ Wv, const float* __restrict__ Wg,
    const float* __restrict__ bq, const float* __restrict__ Wo,
    float* __restrict__ Cout, int mode_sel)
{
    __shared__ float As[2][16][68];
    __shared__ float Bs[2][16][64];
    int mode = (mode_sel < 0) ? (int)blockIdx.z : mode_sel;
    const float* Bm = (mode==0)?Wq:(mode==1)?Wk:(mode==2)?Wv:(mode==3)?Wg:Wo;
    const float* A  = (mode==4)? g_o : g_sln;
    int tid = threadIdx.x;
    int tx = tid & 15, ty = tid >> 4;
    int row0 = blockIdx.y*64, col0 = blockIdx.x*64;
    int arow = tid >> 2, ak = (tid & 3) << 2;
    int bk = tid >> 4, bc = (tid & 15) << 2;
    const float* Aptr = &A[(row0+arow)*DMOD + ak];
    const float* Gptr = &g_gate[(row0+arow)*DMOD + ak];
    const float* Bptr = &Bm[bk*DMOD + col0 + bc];

    float4 av = *(const float4*)Aptr;
    if (mode == 4) {
        float4 gv = *(const float4*)Gptr;
        av.x*=gv.x; av.y*=gv.y; av.z*=gv.z; av.w*=gv.w;
    }
    float4 bv = *(const float4*)Bptr;
    As[0][ak+0][arow]=av.x; As[0][ak+1][arow]=av.y;
    As[0][ak+2][arow]=av.z; As[0][ak+3][arow]=av.w;
    *(float4*)&Bs[0][bk][bc] = bv;
    __syncthreads();

    float acc[4][4] = {};
    int buf = 0;
    for (int k0 = 16; k0 < DMOD; k0 += 16) {
        float4 av2 = *(const float4*)(Aptr + k0);
        if (mode == 4) {
            float4 gv = *(const float4*)(Gptr + k0);
            av2.x*=gv.x; av2.y*=gv.y; av2.z*=gv.z; av2.w*=gv.w;
        }
        float4 bv2 = *(const float4*)(Bptr + (size_t)k0*DMOD);
        #pragma unroll
        for (int kk = 0; kk < 16; kk++) {
            float4 a4 = *(const float4*)&As[buf][kk][ty << 2];
            float4 b4 = *(const float4*)&Bs[buf][kk][tx << 2];
            float ar[4] = {a4.x,a4.y,a4.z,a4.w};
            float br[4] = {b4.x,b4.y,b4.z,b4.w};
            #pragma unroll
            for (int i = 0; i < 4; i++)
                #pragma unroll
                for (int j = 0; j < 4; j++)
                    acc[i][j] = fmaf(ar[i], br[j], acc[i][j]);
        }
        As[buf^1][ak+0][arow]=av2.x; As[buf^1][ak+1][arow]=av2.y;
        As[buf^1][ak+2][arow]=av2.z; As[buf^1][ak+3][arow]=av2.w;
        *(float4*)&Bs[buf^1][bk][bc] = bv2;
        __syncthreads();
        buf ^= 1;
    }
    #pragma unroll
    for (int kk = 0; kk < 16; kk++) {
        float4 a4 = *(const float4*)&As[buf][kk][ty << 2];
        float4 b4 = *(const float4*)&Bs[buf][kk][tx << 2];
        float ar[4] = {a4.x,a4.y,a4.z,a4.w};
        float br[4] = {b4.x,b4.y,b4.z,b4.w};
        #pragma unroll
        for (int i = 0; i < 4; i++)
            #pragma unroll
            for (int j = 0; j < 4; j++)
                acc[i][j] = fmaf(ar[i], br[j], acc[i][j]);
    }

    int row = row0 + (ty << 2), col = col0 + (tx << 2);
    if (mode <= 2) {
        float* dst = (mode == 0) ? g_q : (mode == 1 ? g_k : g_v);
        float bb[4] = {0.f,0.f,0.f,0.f};
        if (mode == 0) {
            float4 bia = *(const float4*)&bq[col];
            bb[0]=bia.x; bb[1]=bia.y; bb[2]=bia.z; bb[3]=bia.w;
        }
        #pragma unroll
        for (int i = 0; i < 4; i++)
            #pragma unroll
            for (int j = 0; j < 4; j++) {
                int cc = col + j;
                float v = acc[i][j];
                if (mode == 0) v = (v + bb[j]) * QSCALE;
                dst[((cc >> 5)*NSEQ + (row + i))*HDIM + (cc & 31)] = v;
            }
    } else if (mode == 3) {
        #pragma unroll
        for (int i = 0; i < 4; i++)
            #pragma unroll
            for (int j = 0; j < 4; j++)
                g_gate[(row+i)*DMOD + col+j] = 1.f/(1.f + __expf(-acc[i][j]));
    } else {
        #pragma unroll
        for (int i = 0; i < 4; i++)
            *(float4*)&Cout[(row+i)*DMOD + col] =
                make_float4(acc[i][0], acc[i][1], acc[i][2], acc[i][3]);
    }
}

// fused LN(z)@Wz -> g_scores[h][q][k]; single pass over z (512 MB)
__global__ __launch_bounds__(256) void zbias_kernel(const float* __restrict__ z)
{
    __shared__ float wz_s[DZ][NHEAD];
    __shared__ float ab_s[2*NHEAD];
    __shared__ float zt[8][32][33];
    int tid = threadIdx.x;
    int lane = tid & 31, w = tid >> 5;
    for (int i = tid; i < DZ*NHEAD; i += 256)
        wz_s[i >> 4][i & 15] = g_wzp[i];
    if (tid < 32) ab_s[tid] = (tid < 16) ? g_alpha[tid] : g_beta[tid - 16];
    __syncthreads();

    int row0w = blockIdx.x*256 + w*32;
    const float* zwarp = z + (size_t)row0w * DZ;
    float acc[NHEAD];
    #pragma unroll
    for (int h = 0; h < NHEAD; h++) acc[h] = 0.f;
    float sum = 0.f, ssq = 0.f;

    for (int ch = 0; ch < 4; ch++) {
        #pragma unroll
        for (int r = 0; r < 32; r++)
            zt[w][r][lane] = zwarp[(size_t)r*DZ + ch*32 + lane];
        __syncwarp();
        #pragma unroll
        for (int c = 0; c < 32; c++) {
            float val = zt[w][lane][c];
            sum += val; ssq += val*val;
            const float* wrow = &wz_s[ch*32 + c][0];
            #pragma unroll
            for (int h4 = 0; h4 < 4; h4++) {
                float4 wv = *(const float4*)&wrow[h4*4];
                acc[h4*4+0] = fmaf(val, wv.x, acc[h4*4+0]);
                acc[h4*4+1] = fmaf(val, wv.y, acc[h4*4+1]);
                acc[h4*4+2] = fmaf(val, wv.z, acc[h4*4+2]);
                acc[h4*4+3] = fmaf(val, wv.w, acc[h4*4+3]);
            }
        }
        __syncwarp();
    }
    float mu = sum * (1.f/DZ);
    float var = ssq * (1.f/DZ) - mu*mu;
    float rstd = rsqrtf(var + 1e-5f);
    int row = row0w + lane;
    #pragma unroll
    for (int h = 0; h < NHEAD; h++)
        g_scores[(size_t)h*NN + row] = rstd*(acc[h] - mu*ab_s[h]) + ab_s[16+h];
}

// Flash attention: one block per (q-tile 64, head). S=QK^T+zb, online softmax, O=P@V.
__global__ __launch_bounds__(256) void flash_kernel()
{
    __shared__ float Qs[32][68];     // [d][qrow]
    __shared__ float Ks[32][68];     // [d][krow]
    __shared__ float Vs[64][36];     // [krow][d]
    __shared__ float Ps[64][68];     // [qrow][kcol]
    __shared__ float corr_s[64];
    __shared__ float l_s[64];
    int tid = threadIdx.x;
    int h = blockIdx.y, q0 = blockIdx.x*64;
    const float* qb = g_q + h*NSEQ*HDIM;
    const float* kp = g_k + h*NSEQ*HDIM;
    const float* vp = g_v + h*NSEQ*HDIM;
    const float* zp = g_scores + (size_t)h*NN;

    int lr = tid >> 2;            // 0..63 (load row)
    int lc = (tid & 3) << 2;      // 0,4,8,12 (load col group)
    {
        float4 a = *(const float4*)&qb[(q0+lr)*HDIM + lc];
        float4 b = *(const float4*)&qb[(q0+lr)*HDIM + lc + 16];
        Qs[lc+0][lr]=a.x; Qs[lc+1][lr]=a.y; Qs[lc+2][lr]=a.z; Qs[lc+3][lr]=a.w;
        Qs[lc+16][lr]=b.x; Qs[lc+17][lr]=b.y; Qs[lc+18][lr]=b.z; Qs[lc+19][lr]=b.w;
    }
    int tx = tid & 15, ty = tid >> 4;       // S-phase: 4 rows x 4 cols
    int oty = tid >> 3, otx = tid & 7;      // O-phase: 2 rows x 4 cols
    int vc = (tid & 3) << 3;                // V load col
    float m[4], l[4];
    #pragma unroll
    for (int i = 0; i < 4; i++) { m[i] = -1e30f; l[i] = 0.f; }
    float oacc[2][4] = {};

    for (int kb0 = 0; kb0 < NSEQ; kb0 += 64) {
        float4 ka = *(const float4*)&kp[(kb0+lr)*HDIM + lc];
        float4 kc2 = *(const float4*)&kp[(kb0+lr)*HDIM + lc + 16];
        float4 v0 = *(const float4*)&vp[(kb0+lr)*HDIM + vc];
        float4 v1 = *(const float4*)&vp[(kb0+lr)*HDIM + vc + 4];
        __syncthreads();    // previous O-phase done with Ks/Vs/Ps
        Ks[lc+0][lr]=ka.x; Ks[lc+1][lr]=ka.y; Ks[lc+2][lr]=ka.z; Ks[lc+3][lr]=ka.w;
        Ks[lc+16][lr]=kc2.x; Ks[lc+17][lr]=kc2.y; Ks[lc+18][lr]=kc2.z; Ks[lc+19][lr]=kc2.w;
        *(float4*)&Vs[lr][vc] = v0;
        *(float4*)&Vs[lr][vc+4] = v1;
        __syncthreads();

        // S = QK^T + zb
        float s[4][4];
        #pragma unroll
        for (int i = 0; i < 4; i++) {
            float4 z4 = *(const float4*)&zp[(size_t)(q0+(ty<<2)+i)*NSEQ + kb0 + (tx<<2)];
            s[i][0]=z4.x; s[i][1]=z4.y; s[i][2]=z4.z; s[i][3]=z4.w;
        }
        #pragma unroll
        for (int kk = 0; kk < 32; kk++) {
            float4 a4 = *(const float4*)&Qs[kk][ty << 2];
            float4 b4 = *(const float4*)&Ks[kk][tx << 2];
            float ar[4] = {a4.x,a4.y,a4.z,a4.w};
            float br[4] = {b4.x,b4.y,b4.z,b4.w};
            #pragma unroll
            for (int i = 0; i < 4; i++)
                #pragma unroll
                for (int j = 0; j < 4; j++)
                    s[i][j] = fmaf(ar[i], br[j], s[i][j]);
        }
        // online softmax (row groups of 16 lanes: lane bits 0..3 = tx)
        #pragma unroll
        for (int i = 0; i < 4; i++) {
            float mx = fmaxf(fmaxf(s[i][0],s[i][1]), fmaxf(s[i][2],s[i][3]));
            mx = fmaxf(mx, __shfl_xor_sync(0xffffffffu, mx, 1));
            mx = fmaxf(mx, __shfl_xor_sync(0xffffffffu, mx, 2));
            mx = fmaxf(mx, __shfl_xor_sync(0xffffffffu, mx, 4));
            mx = fmaxf(mx, __shfl_xor_sync(0xffffffffu, mx, 8));
            float mnew = fmaxf(m[i], mx);
            float c = __expf(m[i] - mnew);
            s[i][0] = __expf(s[i][0]-mnew); s[i][1] = __expf(s[i][1]-mnew);
            s[i][2] = __expf(s[i][2]-mnew); s[i][3] = __expf(s[i][3]-mnew);
            float rs = s[i][0]+s[i][1]+s[i][2]+s[i][3];
            rs += __shfl_xor_sync(0xffffffffu, rs, 1);
            rs += __shfl_xor_sync(0xffffffffu, rs, 2);
            rs += __shfl_xor_sync(0xffffffffu, rs, 4);
            rs += __shfl_xor_sync(0xffffffffu, rs, 8);
            l[i] = l[i]*c + rs;
            m[i] = mnew;
            int row = (ty << 2) + i;
            if (tx == 0) { corr_s[row] = c; l_s[row] = l[i]; }
            *(float4*)&Ps[row][tx << 2] = make_float4(s[i][0],s[i][1],s[i][2],s[i][3]);
        }
        __syncthreads();

        // O = O*corr + P@V
        float c0 = corr_s[oty*2], c1 = corr_s[oty*2+1];
        #pragma unroll
        for (int j = 0; j < 4; j++) { oacc[0][j] *= c0; oacc[1][j] *= c1; }
        #pragma unroll
        for (int kk = 0; kk < 64; kk++) {
            float p0 = Ps[oty*2][kk];
            float p1 = Ps[oty*2+1][kk];
            float4 vv = *(const float4*)&Vs[kk][otx << 2];
            oacc[0][0]=fmaf(p0,vv.x,oacc[0][0]); oacc[0][1]=fmaf(p0,vv.y,oacc[0][1]);
            oacc[0][2]=fmaf(p0,vv.z,oacc[0][2]); oacc[0][3]=fmaf(p0,vv.w,oacc[0][3]);
            oacc[1][0]=fmaf(p1,vv.x,oacc[1][0]); oacc[1][1]=fmaf(p1,vv.y,oacc[1][1]);
            oacc[1][2]=fmaf(p1,vv.z,oacc[1][2]); oacc[1][3]=fmaf(p1,vv.w,oacc[1][3]);
        }
    }
    float inv0 = 1.f / l_s[oty*2];
    float inv1 = 1.f / l_s[oty*2+1];
    *(float4*)&g_o[(q0 + oty*2 + 0)*DMOD + h*HDIM + (otx << 2)] =
        make_float4(oacc[0][0]*inv0, oacc[0][1]*inv0, oacc[0][2]*inv0, oacc[0][3]*inv0);
    *(float4*)&g_o[(q0 + oty*2 + 1)*DMOD + h*HDIM + (otx << 2)] =
        make_float4(oacc[1][0]*inv1, oacc[1][1]*inv1, oacc[1][2]*inv1, oacc[1][3]*inv1);
}

extern "C" void kernel_launch(void* const* d_in, const int* in_sizes, int n_in,
                              void* d_out, int out_size)
{
    const float* s   = (const float*)d_in[0];
    const float* z   = (const float*)d_in[1];
    const float* nsw = (const float*)d_in[2];
    const float* nsb = (const float*)d_in[3];
    const float* Wq  = (const float*)d_in[4];
    const float* bq  = (const float*)d_in[5];
    const float* Wk  = (const float*)d_in[6];
    const float* Wv  = (const float*)d_in[7];
    const float* Wg  = (const float*)d_in[8];
    const float* zw  = (const float*)d_in[9];
    const float* zb  = (const float*)d_in[10];
    const float* Wz  = (const float*)d_in[11];
    const float* Wo  = (const float*)d_in[12];
    float* out = (float*)d_out;

    prep_kernel<<<1, 256>>>(Wz, zw, zb);
    ln_s_kernel<<<NSEQ, 128>>>(s, nsw, nsb);
    gemm_fused<<<dim3(DMOD/64, NSEQ/64, 4), 256>>>(Wq, Wk, Wv, Wg, bq, Wo, nullptr, -1);
    zbias_kernel<<<NN/256, 256>>>(z);
    flash_kernel<<<dim3(NSEQ/64, NHEAD), 256>>>();
    gemm_fused<<<dim3(DMOD/64, NSEQ/64, 1), 256>>>(Wq, Wk, Wv, Wg, bq, Wo, out, 4);
}

// round 5
// speedup vs baseline: 1.3866x; 1.1044x over previous
#include <cuda_runtime.h>
#include <math.h>
#include <stdint.h>

#define NSEQ 1024
#define DMOD 512
#define NHEAD 16
#define HDIM 32
#define DZ 128
#define NN (NSEQ*NSEQ)
#define QSCALE 0.17677669529663687f

__device__ float g_sln[NSEQ*DMOD];
__device__ float g_q[NHEAD*NSEQ*HDIM];
__device__ float g_k[NHEAD*NSEQ*HDIM];
__device__ float g_v[NHEAD*NSEQ*HDIM];
__device__ float g_gate[NSEQ*DMOD];
__device__ float g_o[NSEQ*DMOD];
__device__ float g_scores[NHEAD*NN];   // holds zb only (flash never materializes scores)
__device__ float g_wzp[DZ*NHEAD];
__device__ float g_alpha[NHEAD];
__device__ float g_beta[NHEAD];

// ---- packed f32x2 helpers (Blackwell FFMA2; PTX-only) ----
typedef unsigned long long u64;
__device__ __forceinline__ u64 pk(float x, float y) {
    u64 r; asm("mov.b64 %0, {%1,%2};" : "=l"(r) : "f"(x), "f"(y)); return r;
}
__device__ __forceinline__ void upk(u64 v, float& lo, float& hi) {
    asm("mov.b64 {%0,%1}, %2;" : "=f"(lo), "=f"(hi) : "l"(v));
}
__device__ __forceinline__ void ffma2(u64& d, u64 a, u64 b) {
    asm("fma.rn.f32x2 %0, %1, %2, %0;" : "+l"(d) : "l"(a), "l"(b));
}
__device__ __forceinline__ void fadd2(u64& d, u64 a) {
    asm("add.rn.f32x2 %0, %1, %0;" : "+l"(d) : "l"(a));
}

__global__ void prep_kernel(const float* __restrict__ Wz,
                            const float* __restrict__ zw,
                            const float* __restrict__ zb)
{
    int t = threadIdx.x;
    for (int i = t; i < DZ*NHEAD; i += blockDim.x)
        g_wzp[i] = zw[i >> 4] * Wz[i];
    if (t < NHEAD) {
        float a = 0.f, b = 0.f;
        for (int c = 0; c < DZ; c++) {
            float wv = Wz[c*NHEAD + t];
            a += zw[c] * wv;
            b += zb[c] * wv;
        }
        g_alpha[t] = a;
        g_beta[t]  = b;
    }
}

__global__ __launch_bounds__(128) void ln_s_kernel(const float* __restrict__ s,
                                                   const float* __restrict__ w,
                                                   const float* __restrict__ b)
{
    __shared__ float sred[8];
    __shared__ float s_mu, s_rstd;
    int row = blockIdx.x, tid = threadIdx.x;
    float4 v = *(const float4*)&s[row*DMOD + tid*4];
    float sum = v.x + v.y + v.z + v.w;
    float ssq = v.x*v.x + v.y*v.y + v.z*v.z + v.w*v.w;
    #pragma unroll
    for (int o = 16; o; o >>= 1) {
        sum += __shfl_xor_sync(0xffffffffu, sum, o);
        ssq += __shfl_xor_sync(0xffffffffu, ssq, o);
    }
    int lane = tid & 31, wid = tid >> 5;
    if (lane == 0) { sred[wid] = sum; sred[4 + wid] = ssq; }
    __syncthreads();
    if (tid == 0) {
        float a = sred[0]+sred[1]+sred[2]+sred[3];
        float q = sred[4]+sred[5]+sred[6]+sred[7];
        float mu = a * (1.f/DMOD);
        float var = q * (1.f/DMOD) - mu*mu;
        s_mu = mu; s_rstd = rsqrtf(var + 1e-5f);
    }
    __syncthreads();
    float mu = s_mu, rstd = s_rstd;
    float4 wv = *(const float4*)&w[tid*4];
    float4 bv = *(const float4*)&b[tid*4];
    float4 o;
    o.x = (v.x-mu)*rstd*wv.x + bv.x;
    o.y = (v.y-mu)*rstd*wv.y + bv.y;
    o.z = (v.z-mu)*rstd*wv.z + bv.z;
    o.w = (v.w-mu)*rstd*wv.w + bv.w;
    *(float4*)&g_sln[row*DMOD + tid*4] = o;
}

// Double-buffered 64x64x512 GEMM.
// mode_sel=-1: mode=blockIdx.z (0 q,1 k,2 v,3 gate). mode_sel=4: out=(g_o*g_gate)@Wo.
__global__ __launch_bounds__(256) void gemm_fused(
    const float* __restrict__ Wq, const float* __restrict__ Wk,
    const float* __restrict__ Wv, const float* __restrict__ Wg,
    const float* __restrict__ bq, const float* __restrict__ Wo,
    float* __restrict__ Cout, int mode_sel)
{
    __shared__ float As[2][16][68];
    __shared__ float Bs[2][16][64];
    int mode = (mode_sel < 0) ? (int)blockIdx.z : mode_sel;
    const float* Bm = (mode==0)?Wq:(mode==1)?Wk:(mode==2)?Wv:(mode==3)?Wg:Wo;
    const float* A  = (mode==4)? g_o : g_sln;
    int tid = threadIdx.x;
    int tx = tid & 15, ty = tid >> 4;
    int row0 = blockIdx.y*64, col0 = blockIdx.x*64;
    int arow = tid >> 2, ak = (tid & 3) << 2;
    int bk = tid >> 4, bc = (tid & 15) << 2;
    const float* Aptr = &A[(row0+arow)*DMOD + ak];
    const float* Gptr = &g_gate[(row0+arow)*DMOD + ak];
    const float* Bptr = &Bm[bk*DMOD + col0 + bc];

    float4 av = *(const float4*)Aptr;
    if (mode == 4) {
        float4 gv = *(const float4*)Gptr;
        av.x*=gv.x; av.y*=gv.y; av.z*=gv.z; av.w*=gv.w;
    }
    float4 bv = *(const float4*)Bptr;
    As[0][ak+0][arow]=av.x; As[0][ak+1][arow]=av.y;
    As[0][ak+2][arow]=av.z; As[0][ak+3][arow]=av.w;
    *(float4*)&Bs[0][bk][bc] = bv;
    __syncthreads();

    float acc[4][4] = {};
    int buf = 0;
    for (int k0 = 16; k0 < DMOD; k0 += 16) {
        float4 av2 = *(const float4*)(Aptr + k0);
        if (mode == 4) {
            float4 gv = *(const float4*)(Gptr + k0);
            av2.x*=gv.x; av2.y*=gv.y; av2.z*=gv.z; av2.w*=gv.w;
        }
        float4 bv2 = *(const float4*)(Bptr + (size_t)k0*DMOD);
        #pragma unroll
        for (int kk = 0; kk < 16; kk++) {
            float4 a4 = *(const float4*)&As[buf][kk][ty << 2];
            float4 b4 = *(const float4*)&Bs[buf][kk][tx << 2];
            float ar[4] = {a4.x,a4.y,a4.z,a4.w};
            float br[4] = {b4.x,b4.y,b4.z,b4.w};
            #pragma unroll
            for (int i = 0; i < 4; i++)
                #pragma unroll
                for (int j = 0; j < 4; j++)
                    acc[i][j] = fmaf(ar[i], br[j], acc[i][j]);
        }
        As[buf^1][ak+0][arow]=av2.x; As[buf^1][ak+1][arow]=av2.y;
        As[buf^1][ak+2][arow]=av2.z; As[buf^1][ak+3][arow]=av2.w;
        *(float4*)&Bs[buf^1][bk][bc] = bv2;
        __syncthreads();
        buf ^= 1;
    }
    #pragma unroll
    for (int kk = 0; kk < 16; kk++) {
        float4 a4 = *(const float4*)&As[buf][kk][ty << 2];
        float4 b4 = *(const float4*)&Bs[buf][kk][tx << 2];
        float ar[4] = {a4.x,a4.y,a4.z,a4.w};
        float br[4] = {b4.x,b4.y,b4.z,b4.w};
        #pragma unroll
        for (int i = 0; i < 4; i++)
            #pragma unroll
            for (int j = 0; j < 4; j++)
                acc[i][j] = fmaf(ar[i], br[j], acc[i][j]);
    }

    int row = row0 + (ty << 2), col = col0 + (tx << 2);
    if (mode <= 2) {
        float* dst = (mode == 0) ? g_q : (mode == 1 ? g_k : g_v);
        float bb[4] = {0.f,0.f,0.f,0.f};
        if (mode == 0) {
            float4 bia = *(const float4*)&bq[col];
            bb[0]=bia.x; bb[1]=bia.y; bb[2]=bia.z; bb[3]=bia.w;
        }
        #pragma unroll
        for (int i = 0; i < 4; i++)
            #pragma unroll
            for (int j = 0; j < 4; j++) {
                int cc = col + j;
                float v = acc[i][j];
                if (mode == 0) v = (v + bb[j]) * QSCALE;
                dst[((cc >> 5)*NSEQ + (row + i))*HDIM + (cc & 31)] = v;
            }
    } else if (mode == 3) {
        #pragma unroll
        for (int i = 0; i < 4; i++)
            #pragma unroll
            for (int j = 0; j < 4; j++)
                g_gate[(row+i)*DMOD + col+j] = 1.f/(1.f + __expf(-acc[i][j]));
    } else {
        #pragma unroll
        for (int i = 0; i < 4; i++)
            *(float4*)&Cout[(row+i)*DMOD + col] =
                make_float4(acc[i][0], acc[i][1], acc[i][2], acc[i][3]);
    }
}

// fused LN(z)@Wz -> g_scores[h][q][k]; single pass over z.
// Warp tile = 32 rows x 16 heads; thread tile = 4 rows (ty+8i) x 4 heads (4tx..).
// FFMA2-packed accumulation; LN stats packed over c-pairs.
__global__ __launch_bounds__(256) void zbias_kernel(const float* __restrict__ z)
{
    __shared__ float wz_s[DZ][NHEAD];    // 8 KB [c][h]
    __shared__ float ab_s[2*NHEAD];
    __shared__ float zs[8][32][36];      // 36.9 KB row-major per-warp tile (pad 4)
    int tid = threadIdx.x;
    int lane = tid & 31, w = tid >> 5;
    int tx = lane & 3, ty = lane >> 2;
    for (int i = tid; i < DZ*NHEAD; i += 256)
        wz_s[i >> 4][i & 15] = g_wzp[i];
    if (tid < 32) ab_s[tid] = (tid < 16) ? g_alpha[tid] : g_beta[tid - 16];
    __syncthreads();

    int row0w = blockIdx.x*256 + w*32;
    const float* zwarp = z + (size_t)row0w * DZ;

    u64 acc2[4][2];           // [row i][h-pair]: heads (4tx,4tx+1) and (4tx+2,4tx+3)
    u64 sum2[4], ssq2[4];
    #pragma unroll
    for (int i = 0; i < 4; i++) {
        acc2[i][0] = 0ull; acc2[i][1] = 0ull;
        sum2[i] = 0ull; ssq2[i] = 0ull;
    }
    int lr8 = lane >> 3, lc8 = (lane & 7) << 2;

    for (int ch = 0; ch < 4; ch++) {
        #pragma unroll
        for (int j = 0; j < 8; j++) {
            float4 t = *(const float4*)&zwarp[(size_t)(j*4 + lr8)*DZ + ch*32 + lc8];
            *(float4*)&zs[w][j*4 + lr8][lc8] = t;
        }
        __syncwarp();
        #pragma unroll
        for (int c4 = 0; c4 < 8; c4++) {
            int cg = ch*32 + c4*4;
            u64 wp[4][2];
            #pragma unroll
            for (int cc = 0; cc < 4; cc++) {
                float4 wq = *(const float4*)&wz_s[cg + cc][tx << 2];
                wp[cc][0] = pk(wq.x, wq.y);
                wp[cc][1] = pk(wq.z, wq.w);
            }
            #pragma unroll
            for (int i = 0; i < 4; i++) {
                float4 v = *(const float4*)&zs[w][ty + 8*i][c4 << 2];
                u64 v01 = pk(v.x, v.y), v23 = pk(v.z, v.w);
                fadd2(sum2[i], v01); fadd2(sum2[i], v23);
                ffma2(ssq2[i], v01, v01); ffma2(ssq2[i], v23, v23);
                u64 vv;
                vv = pk(v.x, v.x); ffma2(acc2[i][0], vv, wp[0][0]); ffma2(acc2[i][1], vv, wp[0][1]);
                vv = pk(v.y, v.y); ffma2(acc2[i][0], vv, wp[1][0]); ffma2(acc2[i][1], vv, wp[1][1]);
                vv = pk(v.z, v.z); ffma2(acc2[i][0], vv, wp[2][0]); ffma2(acc2[i][1], vv, wp[2][1]);
                vv = pk(v.w, v.w); ffma2(acc2[i][0], vv, wp[3][0]); ffma2(acc2[i][1], vv, wp[3][1]);
            }
        }
        __syncwarp();
    }

    #pragma unroll
    for (int i = 0; i < 4; i++) {
        float slo, shi, qlo, qhi;
        upk(sum2[i], slo, shi); upk(ssq2[i], qlo, qhi);
        float sum = slo + shi, ssq = qlo + qhi;
        float mu = sum * (1.f/DZ);
        float var = ssq * (1.f/DZ) - mu*mu;
        float rstd = rsqrtf(var + 1e-5f);
        int row = row0w + ty + 8*i;
        float a0, a1, a2, a3;
        upk(acc2[i][0], a0, a1); upk(acc2[i][1], a2, a3);
        int h0 = tx << 2;
        g_scores[(size_t)(h0+0)*NN + row] = rstd*(a0 - mu*ab_s[h0+0]) + ab_s[16+h0+0];
        g_scores[(size_t)(h0+1)*NN + row] = rstd*(a1 - mu*ab_s[h0+1]) + ab_s[16+h0+1];
        g_scores[(size_t)(h0+2)*NN + row] = rstd*(a2 - mu*ab_s[h0+2]) + ab_s[16+h0+2];
        g_scores[(size_t)(h0+3)*NN + row] = rstd*(a3 - mu*ab_s[h0+3]) + ab_s[16+h0+3];
    }
}

// Flash attention: one block per (q-tile 64, head). S=QK^T+zb, online softmax, O=P@V.
__global__ __launch_bounds__(256) void flash_kernel()
{
    __shared__ float Qs[32][68];
    __shared__ float Ks[32][68];
    __shared__ float Vs[64][36];
    __shared__ float Ps[64][68];
    __shared__ float corr_s[64];
    __shared__ float l_s[64];
    int tid = threadIdx.x;
    int h = blockIdx.y, q0 = blockIdx.x*64;
    const float* qb = g_q + h*NSEQ*HDIM;
    const float* kp = g_k + h*NSEQ*HDIM;
    const float* vp = g_v + h*NSEQ*HDIM;
    const float* zp = g_scores + (size_t)h*NN;

    int lr = tid >> 2;
    int lc = (tid & 3) << 2;
    {
        float4 a = *(const float4*)&qb[(q0+lr)*HDIM + lc];
        float4 b = *(const float4*)&qb[(q0+lr)*HDIM + lc + 16];
        Qs[lc+0][lr]=a.x; Qs[lc+1][lr]=a.y; Qs[lc+2][lr]=a.z; Qs[lc+3][lr]=a.w;
        Qs[lc+16][lr]=b.x; Qs[lc+17][lr]=b.y; Qs[lc+18][lr]=b.z; Qs[lc+19][lr]=b.w;
    }
    int tx = tid & 15, ty = tid >> 4;
    int oty = tid >> 3, otx = tid & 7;
    int vc = (tid & 3) << 3;
    float m[4], l[4];
    #pragma unroll
    for (int i = 0; i < 4; i++) { m[i] = -1e30f; l[i] = 0.f; }
    float oacc[2][4] = {};

    for (int kb0 = 0; kb0 < NSEQ; kb0 += 64) {
        float4 ka = *(const float4*)&kp[(kb0+lr)*HDIM + lc];
        float4 kc2 = *(const float4*)&kp[(kb0+lr)*HDIM + lc + 16];
        float4 v0 = *(const float4*)&vp[(kb0+lr)*HDIM + vc];
        float4 v1 = *(const float4*)&vp[(kb0+lr)*HDIM + vc + 4];
        __syncthreads();
        Ks[lc+0][lr]=ka.x; Ks[lc+1][lr]=ka.y; Ks[lc+2][lr]=ka.z; Ks[lc+3][lr]=ka.w;
        Ks[lc+16][lr]=kc2.x; Ks[lc+17][lr]=kc2.y; Ks[lc+18][lr]=kc2.z; Ks[lc+19][lr]=kc2.w;
        *(float4*)&Vs[lr][vc] = v0;
        *(float4*)&Vs[lr][vc+4] = v1;
        __syncthreads();

        float s[4][4];
        #pragma unroll
        for (int i = 0; i < 4; i++) {
            float4 z4 = *(const float4*)&zp[(size_t)(q0+(ty<<2)+i)*NSEQ + kb0 + (tx<<2)];
            s[i][0]=z4.x; s[i][1]=z4.y; s[i][2]=z4.z; s[i][3]=z4.w;
        }
        #pragma unroll
        for (int kk = 0; kk < 32; kk++) {
            float4 a4 = *(const float4*)&Qs[kk][ty << 2];
            float4 b4 = *(const float4*)&Ks[kk][tx << 2];
            float ar[4] = {a4.x,a4.y,a4.z,a4.w};
            float br[4] = {b4.x,b4.y,b4.z,b4.w};
            #pragma unroll
            for (int i = 0; i < 4; i++)
                #pragma unroll
                for (int j = 0; j < 4; j++)
                    s[i][j] = fmaf(ar[i], br[j], s[i][j]);
        }
        #pragma unroll
        for (int i = 0; i < 4; i++) {
            float mx = fmaxf(fmaxf(s[i][0],s[i][1]), fmaxf(s[i][2],s[i][3]));
            mx = fmaxf(mx, __shfl_xor_sync(0xffffffffu, mx, 1));
            mx = fmaxf(mx, __shfl_xor_sync(0xffffffffu, mx, 2));
            mx = fmaxf(mx, __shfl_xor_sync(0xffffffffu, mx, 4));
            mx = fmaxf(mx, __shfl_xor_sync(0xffffffffu, mx, 8));
            float mnew = fmaxf(m[i], mx);
            float c = __expf(m[i] - mnew);
            s[i][0] = __expf(s[i][0]-mnew); s[i][1] = __expf(s[i][1]-mnew);
            s[i][2] = __expf(s[i][2]-mnew); s[i][3] = __expf(s[i][3]-mnew);
            float rs = s[i][0]+s[i][1]+s[i][2]+s[i][3];
            rs += __shfl_xor_sync(0xffffffffu, rs, 1);
            rs += __shfl_xor_sync(0xffffffffu, rs, 2);
            rs += __shfl_xor_sync(0xffffffffu, rs, 4);
            rs += __shfl_xor_sync(0xffffffffu, rs, 8);
            l[i] = l[i]*c + rs;
            m[i] = mnew;
            int row = (ty << 2) + i;
            if (tx == 0) { corr_s[row] = c; l_s[row] = l[i]; }
            *(float4*)&Ps[row][tx << 2] = make_float4(s[i][0],s[i][1],s[i][2],s[i][3]);
        }
        __syncthreads();

        float c0 = corr_s[oty*2], c1 = corr_s[oty*2+1];
        #pragma unroll
        for (int j = 0; j < 4; j++) { oacc[0][j] *= c0; oacc[1][j] *= c1; }
        #pragma unroll
        for (int kk = 0; kk < 64; kk++) {
            float p0 = Ps[oty*2][kk];
            float p1 = Ps[oty*2+1][kk];
            float4 vv = *(const float4*)&Vs[kk][otx << 2];
            oacc[0][0]=fmaf(p0,vv.x,oacc[0][0]); oacc[0][1]=fmaf(p0,vv.y,oacc[0][1]);
            oacc[0][2]=fmaf(p0,vv.z,oacc[0][2]); oacc[0][3]=fmaf(p0,vv.w,oacc[0][3]);
            oacc[1][0]=fmaf(p1,vv.x,oacc[1][0]); oacc[1][1]=fmaf(p1,vv.y,oacc[1][1]);
            oacc[1][2]=fmaf(p1,vv.z,oacc[1][2]); oacc[1][3]=fmaf(p1,vv.w,oacc[1][3]);
        }
    }
    float inv0 = 1.f / l_s[oty*2];
    float inv1 = 1.f / l_s[oty*2+1];
    *(float4*)&g_o[(q0 + oty*2 + 0)*DMOD + h*HDIM + (otx << 2)] =
        make_float4(oacc[0][0]*inv0, oacc[0][1]*inv0, oacc[0][2]*inv0, oacc[0][3]*inv0);
    *(float4*)&g_o[(q0 + oty*2 + 1)*DMOD + h*HDIM + (otx << 2)] =
        make_float4(oacc[1][0]*inv1, oacc[1][1]*inv1, oacc[1][2]*inv1, oacc[1][3]*inv1);
}

extern "C" void kernel_launch(void* const* d_in, const int* in_sizes, int n_in,
                              void* d_out, int out_size)
{
    const float* s   = (const float*)d_in[0];
    const float* z   = (const float*)d_in[1];
    const float* nsw = (const float*)d_in[2];
    const float* nsb = (const float*)d_in[3];
    const float* Wq  = (const float*)d_in[4];
    const float* bq  = (const float*)d_in[5];
    const float* Wk  = (const float*)d_in[6];
    const float* Wv  = (const float*)d_in[7];
    const float* Wg  = (const float*)d_in[8];
    const float* zw  = (const float*)d_in[9];
    const float* zb  = (const float*)d_in[10];
    const float* Wz  = (const float*)d_in[11];
    const float* Wo  = (const float*)d_in[12];
    float* out = (float*)d_out;

    prep_kernel<<<1, 256>>>(Wz, zw, zb);
    ln_s_kernel<<<NSEQ, 128>>>(s, nsw, nsb);
    gemm_fused<<<dim3(DMOD/64, NSEQ/64, 4), 256>>>(Wq, Wk, Wv, Wg, bq, Wo, nullptr, -1);
    zbias_kernel<<<NN/256, 256>>>(z);
    flash_kernel<<<dim3(NSEQ/64, NHEAD), 256>>>();
    gemm_fused<<<dim3(DMOD/64, NSEQ/64, 1), 256>>>(Wq, Wk, Wv, Wg, bq, Wo, out, 4);
}